// round 13
// baseline (speedup 1.0000x reference)
#include <cuda_runtime.h>
#include <math.h>

#define BSZ   2
#define TLEN  2048
#define DM    1024
#define NH    16
#define HD    64
#define MTOT  (BSZ * TLEN)   // 4096

// ---------------- scratch (device globals; no allocations) ----------------
__device__ float g_q [MTOT * DM];
__device__ float g_k [MTOT * DM];
__device__ float g_v [MTOT * DM];
__device__ float g_ao[MTOT * DM];
__device__ float g_cos[TLEN * 32];
__device__ float g_sin[TLEN * 32];

// ---------------- RoPE table (double-precision arg -> exact-ish cos/sin) --
__global__ void rope_table_kernel() {
    int idx = blockIdx.x * blockDim.x + threadIdx.x;
    if (idx >= TLEN * 32) return;
    int t = idx >> 5;
    int i = idx & 31;
    double inv = pow(10000.0, -((double)(2 * i)) / 64.0);
    double f = (double)t * inv;
    g_cos[idx] = (float)cos(f);
    g_sin[idx] = (float)sin(f);
}

// ---------------- SGEMM: C[M,N] = A[M,K] @ B[K,N], all row-major ----------
// 128x128 block tile, BK=8, 256 threads, 8x8 per-thread microtile.
__global__ __launch_bounds__(256) void sgemm128(
    const float* __restrict__ A, const float* __restrict__ B,
    float* __restrict__ C, int M, int N, int K)
{
    const int BK = 8;
    __shared__ float As[BK][128];
    __shared__ float Bs[BK][128];

    int tid = threadIdx.x;
    int tx = tid & 15, ty = tid >> 4;
    int rowBase = blockIdx.y * 128;
    int colBase = blockIdx.x * 128;

    int aRow = tid >> 1;
    int aCol = (tid & 1) * 4;
    int bRow = tid >> 5;
    int bCol = (tid & 31) * 4;

    const float* Aptr = A + (size_t)(rowBase + aRow) * K + aCol;
    const float* Bptr = B + (size_t)bRow * N + colBase + bCol;

    float acc[8][8];
#pragma unroll
    for (int i = 0; i < 8; i++)
#pragma unroll
        for (int j = 0; j < 8; j++) acc[i][j] = 0.f;

    for (int k0 = 0; k0 < K; k0 += BK) {
        float4 a4 = *(const float4*)Aptr;
        As[aCol + 0][aRow] = a4.x;
        As[aCol + 1][aRow] = a4.y;
        As[aCol + 2][aRow] = a4.z;
        As[aCol + 3][aRow] = a4.w;
        *(float4*)&Bs[bRow][bCol] = *(const float4*)Bptr;
        __syncthreads();

#pragma unroll
        for (int k = 0; k < BK; k++) {
            float ra[8], rb[8];
            *(float4*)(ra)     = *(float4*)&As[k][ty * 8];
            *(float4*)(ra + 4) = *(float4*)&As[k][ty * 8 + 4];
            *(float4*)(rb)     = *(float4*)&Bs[k][tx * 8];
            *(float4*)(rb + 4) = *(float4*)&Bs[k][tx * 8 + 4];
#pragma unroll
            for (int i = 0; i < 8; i++)
#pragma unroll
                for (int j = 0; j < 8; j++)
                    acc[i][j] += ra[i] * rb[j];
        }
        __syncthreads();
        Aptr += BK;
        Bptr += (size_t)BK * N;
    }

#pragma unroll
    for (int i = 0; i < 8; i++) {
        float* crow = C + (size_t)(rowBase + ty * 8 + i) * N + colBase + tx * 8;
        float4 v0 = make_float4(acc[i][0], acc[i][1], acc[i][2], acc[i][3]);
        float4 v1 = make_float4(acc[i][4], acc[i][5], acc[i][6], acc[i][7]);
        *(float4*)(crow)     = v0;
        *(float4*)(crow + 4) = v1;
    }
}

// ---------------- fused per-head RMSNorm + RoPE (in place on g_q / g_k) ---
// one warp per (tensor, b, t, h) head-row; lane i holds elements (i, i+32)
__global__ void norm_rope_kernel(const float* __restrict__ qw,
                                 const float* __restrict__ kw)
{
    int gw = (blockIdx.x * blockDim.x + threadIdx.x) >> 5;  // 0..131071
    int lane = threadIdx.x & 31;
    int which = gw >> 16;       // 0 = q, 1 = k  (65536 rows each)
    int row = gw & 65535;       // (b*T + t)*H + h
    float* base = which ? g_k : g_q;
    const float* w = which ? kw : qw;

    int bt = row / NH;
    int h  = row % NH;
    int t  = bt % TLEN;

    float* p = base + (size_t)bt * DM + h * HD;
    float x1 = p[lane];
    float x2 = p[lane + 32];

    float ss = x1 * x1 + x2 * x2;
#pragma unroll
    for (int o = 16; o; o >>= 1) ss += __shfl_xor_sync(0xffffffffu, ss, o);
    float r = rsqrtf(ss * (1.0f / 64.0f) + 1e-6f);

    float c = g_cos[t * 32 + lane];
    float s = g_sin[t * 32 + lane];
    float x1n = x1 * r * w[lane];
    float x2n = x2 * r * w[lane + 32];
    p[lane]      = x1n * c - x2n * s;
    p[lane + 32] = x2n * c + x1n * s;
}

// ---------------- flash attention (causal, fp32, 64x64 tiles) -------------
#define FP    68                        // padded row stride (floats)
#define SM_Q  0
#define SM_KT (64 * FP)
#define SM_V  (2 * 64 * FP)
#define SM_P  (3 * 64 * FP)
#define SM_M  (4 * 64 * FP)
#define SM_L  (SM_M + 64)
#define SM_A  (SM_L + 64)
#define FLASH_SMEM ((4 * 64 * FP + 3 * 64) * 4)

__global__ __launch_bounds__(256) void flash_kernel()
{
    extern __shared__ float sm[];
    float* Qs  = sm + SM_Q;   // [row][d]
    float* KsT = sm + SM_KT;  // [d][k-col]  (transposed)
    float* Vs  = sm + SM_V;   // [k][d]
    float* Ps  = sm + SM_P;   // [row][k]
    float* mrow = sm + SM_M;
    float* lrow = sm + SM_L;
    float* arow = sm + SM_A;

    int qt = gridDim.x - 1 - blockIdx.x;   // longest blocks first
    int bh = blockIdx.y;
    int b = bh / NH, h = bh % NH;
    int tid = threadIdx.x;
    int tx = tid & 15, ty = tid >> 4;

    const float* qbase = g_q + (size_t)(b * TLEN) * DM + h * HD;
    const float* kbase = g_k + (size_t)(b * TLEN) * DM + h * HD;
    const float* vbase = g_v + (size_t)(b * TLEN) * DM + h * HD;

    // load Q tile (64 rows x 64 dims)
    for (int it = tid; it < 64 * 16; it += 256) {
        int r = it >> 4;
        int c4 = (it & 15) << 2;
        float4 v = *(const float4*)(qbase + (size_t)(qt * 64 + r) * DM + c4);
        *(float4*)&Qs[r * FP + c4] = v;
    }
    if (tid < 64) { mrow[tid] = -INFINITY; lrow[tid] = 0.f; }

    float o[4][4];
#pragma unroll
    for (int i = 0; i < 4; i++)
#pragma unroll
        for (int j = 0; j < 4; j++) o[i][j] = 0.f;

    const float scale = 0.125f;  // 1/sqrt(64)

    for (int kt = 0; kt <= qt; kt++) {
        __syncthreads();  // protect KsT/Vs/Ps from previous iter, and Q load on iter 0

        // load K (transposed) and V tiles
        for (int it = tid; it < 64 * 16; it += 256) {
            int r = it >> 4;
            int c4 = (it & 15) << 2;
            const float* kp = kbase + (size_t)(kt * 64 + r) * DM + c4;
            float4 kv = *(const float4*)kp;
            KsT[(c4 + 0) * FP + r] = kv.x;
            KsT[(c4 + 1) * FP + r] = kv.y;
            KsT[(c4 + 2) * FP + r] = kv.z;
            KsT[(c4 + 3) * FP + r] = kv.w;
            const float* vp = vbase + (size_t)(kt * 64 + r) * DM + c4;
            *(float4*)&Vs[r * FP + c4] = *(const float4*)vp;
        }
        __syncthreads();

        // S = scale * Q K^T  (each thread: 4 rows x 4 cols)
        float s[4][4];
#pragma unroll
        for (int i = 0; i < 4; i++)
#pragma unroll
            for (int j = 0; j < 4; j++) s[i][j] = 0.f;

#pragma unroll 8
        for (int d = 0; d < 64; d++) {
            float4 k4 = *(const float4*)&KsT[d * FP + tx * 4];
#pragma unroll
            for (int ii = 0; ii < 4; ii++) {
                float qv = Qs[(ty * 4 + ii) * FP + d];
                s[ii][0] += qv * k4.x;
                s[ii][1] += qv * k4.y;
                s[ii][2] += qv * k4.z;
                s[ii][3] += qv * k4.w;
            }
        }

        bool diag = (kt == qt);
        float rmax[4];
#pragma unroll
        for (int ii = 0; ii < 4; ii++) {
            rmax[ii] = -INFINITY;
#pragma unroll
            for (int jj = 0; jj < 4; jj++) {
                float v = s[ii][jj] * scale;
                if (diag && (tx * 4 + jj) > (ty * 4 + ii)) v = -INFINITY;
                s[ii][jj] = v;
                rmax[ii] = fmaxf(rmax[ii], v);
            }
#pragma unroll
            for (int off = 8; off; off >>= 1)
                rmax[ii] = fmaxf(rmax[ii], __shfl_xor_sync(0xffffffffu, rmax[ii], off));
        }
        if (tx == 0) {
#pragma unroll
            for (int ii = 0; ii < 4; ii++) {
                int i = ty * 4 + ii;
                float mo = mrow[i];
                float mn = fmaxf(mo, rmax[ii]);
                mrow[i] = mn;
                arow[i] = expf(mo - mn);
            }
        }
        __syncthreads();  // stats ready

        float rsum[4];
#pragma unroll
        for (int ii = 0; ii < 4; ii++) {
            int i = ty * 4 + ii;
            float mi = mrow[i];
            float a  = arow[i];
            rsum[ii] = 0.f;
#pragma unroll
            for (int jj = 0; jj < 4; jj++) {
                float p = expf(s[ii][jj] - mi);
                Ps[i * FP + tx * 4 + jj] = p;
                rsum[ii] += p;
                o[ii][jj] *= a;  // rescale accumulator
            }
#pragma unroll
            for (int off = 8; off; off >>= 1)
                rsum[ii] += __shfl_xor_sync(0xffffffffu, rsum[ii], off);
        }
        if (tx == 0) {
#pragma unroll
            for (int ii = 0; ii < 4; ii++) {
                int i = ty * 4 + ii;
                lrow[i] = lrow[i] * arow[i] + rsum[ii];
            }
        }
        __syncthreads();  // Ps ready

        // O += P V
#pragma unroll 8
        for (int kk = 0; kk < 64; kk++) {
            float4 v4 = *(const float4*)&Vs[kk * FP + tx * 4];
#pragma unroll
            for (int ii = 0; ii < 4; ii++) {
                float pv = Ps[(ty * 4 + ii) * FP + kk];
                o[ii][0] += pv * v4.x;
                o[ii][1] += pv * v4.y;
                o[ii][2] += pv * v4.z;
                o[ii][3] += pv * v4.w;
            }
        }
    }

    // write out: [B, T, H*hd]
#pragma unroll
    for (int ii = 0; ii < 4; ii++) {
        int i = ty * 4 + ii;
        float inv = 1.0f / lrow[i];
        int row = qt * 64 + i;
        float4 ov = make_float4(o[ii][0] * inv, o[ii][1] * inv,
                                o[ii][2] * inv, o[ii][3] * inv);
        *(float4*)(g_ao + (size_t)(b * TLEN + row) * DM + h * HD + tx * 4) = ov;
    }
}

// ---------------- launch ---------------------------------------------------
extern "C" void kernel_launch(void* const* d_in, const int* in_sizes, int n_in,
                              void* d_out, int out_size)
{
    const float* x  = (const float*)d_in[0];
    const float* Wq = (const float*)d_in[1];
    const float* Wk = (const float*)d_in[2];
    const float* Wv = (const float*)d_in[3];
    const float* Wo = (const float*)d_in[4];
    const float* qw = (const float*)d_in[5];
    const float* kw = (const float*)d_in[6];
    float* out = (float*)d_out;

    cudaFuncSetAttribute(flash_kernel,
                         cudaFuncAttributeMaxDynamicSharedMemorySize,
                         FLASH_SMEM);

    void *pq, *pk, *pv, *pao;
    cudaGetSymbolAddress(&pq,  g_q);
    cudaGetSymbolAddress(&pk,  g_k);
    cudaGetSymbolAddress(&pv,  g_v);
    cudaGetSymbolAddress(&pao, g_ao);

    // 1. RoPE table
    rope_table_kernel<<<64, 1024>>>();

    // 2. QKV projections
    dim3 gg(DM / 128, MTOT / 128);  // (8, 32)
    sgemm128<<<gg, 256>>>(x, Wq, (float*)pq, MTOT, DM, DM);
    sgemm128<<<gg, 256>>>(x, Wk, (float*)pk, MTOT, DM, DM);
    sgemm128<<<gg, 256>>>(x, Wv, (float*)pv, MTOT, DM, DM);

    // 3. RMSNorm + RoPE on q and k (131072 warps)
    norm_rope_kernel<<<(2 * MTOT * NH) / 8, 256>>>(qw, kw);

    // 4. causal flash attention
    flash_kernel<<<dim3(TLEN / 64, BSZ * NH), 256, FLASH_SMEM>>>();

    // 5. output projection
    sgemm128<<<gg, 256>>>((const float*)pao, Wo, out, MTOT, DM, DM);
}

// round 15
// speedup vs baseline: 1.5053x; 1.5053x over previous
#include <cuda_runtime.h>
#include <cuda_bf16.h>
#include <math.h>
#include <stdint.h>

#define BSZ   2
#define TLEN  2048
#define DM    1024
#define NH    16
#define HD    64
#define MTOT  (BSZ * TLEN)   // 4096

// ---------------- scratch (device globals; no allocations) ----------------
__device__ float g_q [MTOT * DM];
__device__ float g_k [MTOT * DM];
__device__ float g_v [MTOT * DM];
__device__ float g_ao[MTOT * DM];
__device__ float g_cos[TLEN * 32];
__device__ float g_sin[TLEN * 32];

// bf16 hi/lo split operands for tensor-core GEMMs
__device__ __nv_bfloat16 g_xh [MTOT * DM];
__device__ __nv_bfloat16 g_xl [MTOT * DM];
__device__ __nv_bfloat16 g_aoh[MTOT * DM];
__device__ __nv_bfloat16 g_aol[MTOT * DM];
// transposed weights (Wt[n][k] = W[k][n]), hi/lo, for Wq,Wk,Wv,Wo
__device__ __nv_bfloat16 g_wth[4][DM * DM];
__device__ __nv_bfloat16 g_wtl[4][DM * DM];

// ================= helpers ==================================================
__device__ __forceinline__ uint32_t smem_u32(const void* p) {
    uint32_t a;
    asm("{ .reg .u64 t; cvta.to.shared.u64 t, %1; cvt.u32.u64 %0, t; }"
        : "=r"(a) : "l"(p));
    return a;
}
__device__ __forceinline__ void cp16(uint32_t s, const void* g) {
    asm volatile("cp.async.ca.shared.global [%0], [%1], 16;" :: "r"(s), "l"(g));
}
#define CP_COMMIT() asm volatile("cp.async.commit_group;" ::: "memory")
#define CP_WAIT(n)  asm volatile("cp.async.wait_group %0;" :: "n"(n) : "memory")

__device__ __forceinline__ void ldm_x4(uint32_t* r, uint32_t addr) {
    asm volatile("ldmatrix.sync.aligned.m8n8.x4.shared.b16 {%0,%1,%2,%3}, [%4];"
                 : "=r"(r[0]), "=r"(r[1]), "=r"(r[2]), "=r"(r[3]) : "r"(addr));
}
__device__ __forceinline__ void mma16816(float* d, const uint32_t* a,
                                         uint32_t b0, uint32_t b1) {
    asm volatile(
        "mma.sync.aligned.m16n8k16.row.col.f32.bf16.bf16.f32 "
        "{%0,%1,%2,%3}, {%4,%5,%6,%7}, {%8,%9}, {%0,%1,%2,%3};"
        : "+f"(d[0]), "+f"(d[1]), "+f"(d[2]), "+f"(d[3])
        : "r"(a[0]), "r"(a[1]), "r"(a[2]), "r"(a[3]), "r"(b0), "r"(b1));
}

// ---------------- RoPE table ----------------------------------------------
__global__ void rope_table_kernel() {
    int idx = blockIdx.x * blockDim.x + threadIdx.x;
    if (idx >= TLEN * 32) return;
    int t = idx >> 5;
    int i = idx & 31;
    double inv = pow(10000.0, -((double)(2 * i)) / 64.0);
    double f = (double)t * inv;
    g_cos[idx] = (float)cos(f);
    g_sin[idx] = (float)sin(f);
}

// ---------------- fp32 -> bf16 hi/lo split ---------------------------------
__global__ void split_kernel(const float* __restrict__ in,
                             __nv_bfloat16* __restrict__ h,
                             __nv_bfloat16* __restrict__ l, int n)
{
    int i = blockIdx.x * blockDim.x + threadIdx.x;
    if (i >= n) return;
    float v = in[i];
    __nv_bfloat16 hb = __float2bfloat16_rn(v);
    h[i] = hb;
    l[i] = __float2bfloat16_rn(v - __bfloat162float(hb));
}

// ---------------- W[k][n] -> Wt[n][k] transpose + hi/lo split --------------
__global__ void transpose_split_kernel(const float* __restrict__ W,
                                       __nv_bfloat16* __restrict__ th,
                                       __nv_bfloat16* __restrict__ tl)
{
    __shared__ float tile[32][33];
    int x = blockIdx.x * 32 + threadIdx.x;
    int y0 = blockIdx.y * 32 + threadIdx.y;
#pragma unroll
    for (int i = 0; i < 32; i += 8)
        tile[threadIdx.y + i][threadIdx.x] = W[(size_t)(y0 + i) * DM + x];
    __syncthreads();
    int nx = blockIdx.y * 32 + threadIdx.x;
    int ny0 = blockIdx.x * 32 + threadIdx.y;
#pragma unroll
    for (int i = 0; i < 32; i += 8) {
        float v = tile[threadIdx.x][threadIdx.y + i];
        __nv_bfloat16 hb = __float2bfloat16_rn(v);
        th[(size_t)(ny0 + i) * DM + nx] = hb;
        tl[(size_t)(ny0 + i) * DM + nx] =
            __float2bfloat16_rn(v - __bfloat162float(hb));
    }
}

// ---------------- split-bf16 tensor-core GEMM -------------------------------
// C[M,N] = A[M,K] @ Wt^T.  A given as (Ah + Al), Wt as (Bh + Bl), both
// row-major with K contiguous.  Products hh + hl + lh accumulated in fp32.
// 128x128 CTA tile, BK=32, 8 warps (2x4), warp tile 64x32, cp.async pipeline.
#define GLDA   40                      // padded row stride (bf16 elems)
#define GTILEB (128 * GLDA * 2)        // 10240 B per tensor tile
#define GSTAGE (4 * GTILEB)            // 40960 B per stage
#define GSMEM  (2 * GSTAGE)            // 81920 B total

__device__ __forceinline__ void gemm_prefetch(
    uint32_t sbase, int stage,
    const __nv_bfloat16* Ah, const __nv_bfloat16* Al,
    const __nv_bfloat16* Bh, const __nv_bfloat16* Bl,
    int tileM, int tileN, int k0, int tid)
{
    uint32_t st = sbase + stage * GSTAGE;
#pragma unroll
    for (int i = 0; i < 8; i++) {
        int c = tid + i * 256;         // 0..2047
        int tensor = c >> 9;           // 0..3
        int idx = c & 511;
        int row = idx >> 2;
        int col = (idx & 3) * 8;       // bf16 elem offset
        uint32_t soff = st + tensor * GTILEB + row * 80 + (idx & 3) * 16;
        const __nv_bfloat16* gp;
        if (tensor == 0)      gp = Ah + (size_t)(tileM + row) * DM + k0 + col;
        else if (tensor == 1) gp = Al + (size_t)(tileM + row) * DM + k0 + col;
        else if (tensor == 2) gp = Bh + (size_t)(tileN + row) * DM + k0 + col;
        else                  gp = Bl + (size_t)(tileN + row) * DM + k0 + col;
        cp16(soff, gp);
    }
}

__device__ __forceinline__ void gemm_body(
    const __nv_bfloat16* Ah, const __nv_bfloat16* Al,
    const __nv_bfloat16* Bh, const __nv_bfloat16* Bl,
    float* __restrict__ C, char* smraw)
{
    uint32_t sbase = smem_u32(smraw);
    int tid = threadIdx.x;
    int wid = tid >> 5, lane = tid & 31;
    int tileM = blockIdx.y * 128;
    int tileN = blockIdx.x * 128;
    int wm = (wid >> 2) * 64;
    int wn = (wid & 3) * 32;

    float acc[4][4][4];
#pragma unroll
    for (int i = 0; i < 4; i++)
#pragma unroll
        for (int j = 0; j < 4; j++)
#pragma unroll
            for (int r = 0; r < 4; r++) acc[i][j][r] = 0.f;

    gemm_prefetch(sbase, 0, Ah, Al, Bh, Bl, tileM, tileN, 0, tid);
    CP_COMMIT();

    int arow = lane & 15;
    int acol = (lane >> 4) * 8;
    int brow = ((lane >> 4) << 3) + (lane & 7);
    int bcol = ((lane >> 3) & 1) * 8;

    for (int c = 0; c < 32; c++) {
        if (c < 31) {
            gemm_prefetch(sbase, (c + 1) & 1, Ah, Al, Bh, Bl,
                          tileM, tileN, (c + 1) * 32, tid);
            CP_COMMIT();
            CP_WAIT(1);
        } else {
            CP_WAIT(0);
        }
        __syncthreads();

        uint32_t st = sbase + (c & 1) * GSTAGE;
#pragma unroll
        for (int kk = 0; kk < 32; kk += 16) {
            uint32_t ah[4][4], al[4][4];
#pragma unroll
            for (int mt = 0; mt < 4; mt++) {
                uint32_t ad = st + ((wm + mt * 16 + arow) * GLDA + kk + acol) * 2;
                ldm_x4(ah[mt], ad);
                ldm_x4(al[mt], ad + GTILEB);
            }
            uint32_t bh[2][4], bl[2][4];
#pragma unroll
            for (int p = 0; p < 2; p++) {
                uint32_t bd = st + 2 * GTILEB +
                              ((wn + p * 16 + brow) * GLDA + kk + bcol) * 2;
                ldm_x4(bh[p], bd);
                ldm_x4(bl[p], bd + GTILEB);
            }
#pragma unroll
            for (int mt = 0; mt < 4; mt++)
#pragma unroll
                for (int nt = 0; nt < 4; nt++) {
                    int p = nt >> 1, o = (nt & 1) * 2;
                    mma16816(acc[mt][nt], ah[mt], bh[p][o], bh[p][o + 1]);
                    mma16816(acc[mt][nt], ah[mt], bl[p][o], bl[p][o + 1]);
                    mma16816(acc[mt][nt], al[mt], bh[p][o], bh[p][o + 1]);
                }
        }
        __syncthreads();
    }

    // epilogue
#pragma unroll
    for (int mt = 0; mt < 4; mt++) {
        int row = tileM + wm + mt * 16 + (lane >> 2);
#pragma unroll
        for (int nt = 0; nt < 4; nt++) {
            int col = tileN + wn + nt * 8 + (lane & 3) * 2;
            float2 v0 = make_float2(acc[mt][nt][0], acc[mt][nt][1]);
            float2 v1 = make_float2(acc[mt][nt][2], acc[mt][nt][3]);
            *(float2*)(C + (size_t)row * DM + col)       = v0;
            *(float2*)(C + (size_t)(row + 8) * DM + col) = v1;
        }
    }
}

// fused QKV: blockIdx.z selects weight slot and destination
__global__ __launch_bounds__(256) void bgemm_qkv_kernel(
    const __nv_bfloat16* __restrict__ Ah, const __nv_bfloat16* __restrict__ Al,
    float* __restrict__ C0, float* __restrict__ C1, float* __restrict__ C2)
{
    extern __shared__ char smraw[];
    int z = blockIdx.z;
    float* C = (z == 0) ? C0 : (z == 1) ? C1 : C2;
    gemm_body(Ah, Al, g_wth[z], g_wtl[z], C, smraw);
}

__global__ __launch_bounds__(256) void bgemm_o_kernel(
    const __nv_bfloat16* __restrict__ Ah, const __nv_bfloat16* __restrict__ Al,
    float* __restrict__ C)
{
    extern __shared__ char smraw[];
    gemm_body(Ah, Al, g_wth[3], g_wtl[3], C, smraw);
}

// ---------------- fused per-head RMSNorm + RoPE ----------------------------
__global__ void norm_rope_kernel(const float* __restrict__ qw,
                                 const float* __restrict__ kw)
{
    int gw = (blockIdx.x * blockDim.x + threadIdx.x) >> 5;
    int lane = threadIdx.x & 31;
    int which = gw >> 16;
    int row = gw & 65535;
    float* base = which ? g_k : g_q;
    const float* w = which ? kw : qw;

    int bt = row / NH;
    int h  = row % NH;
    int t  = bt % TLEN;

    float* p = base + (size_t)bt * DM + h * HD;
    float x1 = p[lane];
    float x2 = p[lane + 32];

    float ss = x1 * x1 + x2 * x2;
#pragma unroll
    for (int o = 16; o; o >>= 1) ss += __shfl_xor_sync(0xffffffffu, ss, o);
    float r = rsqrtf(ss * (1.0f / 64.0f) + 1e-6f);

    float c = g_cos[t * 32 + lane];
    float s = g_sin[t * 32 + lane];
    float x1n = x1 * r * w[lane];
    float x2n = x2 * r * w[lane + 32];
    p[lane]      = x1n * c - x2n * s;
    p[lane + 32] = x2n * c + x1n * s;
}

// ---------------- flash attention (causal, fp32, 64x64 tiles) --------------
#define FP    68
#define SM_Q  0
#define SM_KT (64 * FP)
#define SM_V  (2 * 64 * FP)
#define SM_P  (3 * 64 * FP)
#define SM_M  (4 * 64 * FP)
#define SM_L  (SM_M + 64)
#define SM_A  (SM_L + 64)
#define FLASH_SMEM ((4 * 64 * FP + 3 * 64) * 4)

__global__ __launch_bounds__(256) void flash_kernel()
{
    extern __shared__ float sm[];
    float* Qs  = sm + SM_Q;
    float* KsT = sm + SM_KT;
    float* Vs  = sm + SM_V;
    float* Ps  = sm + SM_P;
    float* mrow = sm + SM_M;
    float* lrow = sm + SM_L;
    float* arow = sm + SM_A;

    int qt = gridDim.x - 1 - blockIdx.x;
    int bh = blockIdx.y;
    int b = bh / NH, h = bh % NH;
    int tid = threadIdx.x;
    int tx = tid & 15, ty = tid >> 4;

    const float* qbase = g_q + (size_t)(b * TLEN) * DM + h * HD;
    const float* kbase = g_k + (size_t)(b * TLEN) * DM + h * HD;
    const float* vbase = g_v + (size_t)(b * TLEN) * DM + h * HD;

    for (int it = tid; it < 64 * 16; it += 256) {
        int r = it >> 4;
        int c4 = (it & 15) << 2;
        float4 v = *(const float4*)(qbase + (size_t)(qt * 64 + r) * DM + c4);
        *(float4*)&Qs[r * FP + c4] = v;
    }
    if (tid < 64) { mrow[tid] = -INFINITY; lrow[tid] = 0.f; }

    float o[4][4];
#pragma unroll
    for (int i = 0; i < 4; i++)
#pragma unroll
        for (int j = 0; j < 4; j++) o[i][j] = 0.f;

    const float scale = 0.125f;

    for (int kt = 0; kt <= qt; kt++) {
        __syncthreads();
        for (int it = tid; it < 64 * 16; it += 256) {
            int r = it >> 4;
            int c4 = (it & 15) << 2;
            const float* kp = kbase + (size_t)(kt * 64 + r) * DM + c4;
            float4 kv = *(const float4*)kp;
            KsT[(c4 + 0) * FP + r] = kv.x;
            KsT[(c4 + 1) * FP + r] = kv.y;
            KsT[(c4 + 2) * FP + r] = kv.z;
            KsT[(c4 + 3) * FP + r] = kv.w;
            const float* vp = vbase + (size_t)(kt * 64 + r) * DM + c4;
            *(float4*)&Vs[r * FP + c4] = *(const float4*)vp;
        }
        __syncthreads();

        float s[4][4];
#pragma unroll
        for (int i = 0; i < 4; i++)
#pragma unroll
            for (int j = 0; j < 4; j++) s[i][j] = 0.f;

#pragma unroll 8
        for (int d = 0; d < 64; d++) {
            float4 k4 = *(const float4*)&KsT[d * FP + tx * 4];
#pragma unroll
            for (int ii = 0; ii < 4; ii++) {
                float qv = Qs[(ty * 4 + ii) * FP + d];
                s[ii][0] += qv * k4.x;
                s[ii][1] += qv * k4.y;
                s[ii][2] += qv * k4.z;
                s[ii][3] += qv * k4.w;
            }
        }

        bool diag = (kt == qt);
        float rmax[4];
#pragma unroll
        for (int ii = 0; ii < 4; ii++) {
            rmax[ii] = -INFINITY;
#pragma unroll
            for (int jj = 0; jj < 4; jj++) {
                float v = s[ii][jj] * scale;
                if (diag && (tx * 4 + jj) > (ty * 4 + ii)) v = -INFINITY;
                s[ii][jj] = v;
                rmax[ii] = fmaxf(rmax[ii], v);
            }
#pragma unroll
            for (int off = 8; off; off >>= 1)
                rmax[ii] = fmaxf(rmax[ii], __shfl_xor_sync(0xffffffffu, rmax[ii], off));
        }
        if (tx == 0) {
#pragma unroll
            for (int ii = 0; ii < 4; ii++) {
                int i = ty * 4 + ii;
                float mo = mrow[i];
                float mn = fmaxf(mo, rmax[ii]);
                mrow[i] = mn;
                arow[i] = expf(mo - mn);
            }
        }
        __syncthreads();

        float rsum[4];
#pragma unroll
        for (int ii = 0; ii < 4; ii++) {
            int i = ty * 4 + ii;
            float mi = mrow[i];
            float a  = arow[i];
            rsum[ii] = 0.f;
#pragma unroll
            for (int jj = 0; jj < 4; jj++) {
                float p = expf(s[ii][jj] - mi);
                Ps[i * FP + tx * 4 + jj] = p;
                rsum[ii] += p;
                o[ii][jj] *= a;
            }
#pragma unroll
            for (int off = 8; off; off >>= 1)
                rsum[ii] += __shfl_xor_sync(0xffffffffu, rsum[ii], off);
        }
        if (tx == 0) {
#pragma unroll
            for (int ii = 0; ii < 4; ii++) {
                int i = ty * 4 + ii;
                lrow[i] = lrow[i] * arow[i] + rsum[ii];
            }
        }
        __syncthreads();

#pragma unroll 8
        for (int kk = 0; kk < 64; kk++) {
            float4 v4 = *(const float4*)&Vs[kk * FP + tx * 4];
#pragma unroll
            for (int ii = 0; ii < 4; ii++) {
                float pv = Ps[(ty * 4 + ii) * FP + kk];
                o[ii][0] += pv * v4.x;
                o[ii][1] += pv * v4.y;
                o[ii][2] += pv * v4.z;
                o[ii][3] += pv * v4.w;
            }
        }
    }

#pragma unroll
    for (int ii = 0; ii < 4; ii++) {
        int i = ty * 4 + ii;
        float inv = 1.0f / lrow[i];
        int row = qt * 64 + i;
        float4 ov = make_float4(o[ii][0] * inv, o[ii][1] * inv,
                                o[ii][2] * inv, o[ii][3] * inv);
        *(float4*)(g_ao + (size_t)(b * TLEN + row) * DM + h * HD + tx * 4) = ov;
    }
}

// ---------------- launch ----------------------------------------------------
extern "C" void kernel_launch(void* const* d_in, const int* in_sizes, int n_in,
                              void* d_out, int out_size)
{
    const float* x  = (const float*)d_in[0];
    const float* Wq = (const float*)d_in[1];
    const float* Wk = (const float*)d_in[2];
    const float* Wv = (const float*)d_in[3];
    const float* Wo = (const float*)d_in[4];
    const float* qw = (const float*)d_in[5];
    const float* kw = (const float*)d_in[6];
    float* out = (float*)d_out;

    cudaFuncSetAttribute(flash_kernel,
                         cudaFuncAttributeMaxDynamicSharedMemorySize, FLASH_SMEM);
    cudaFuncSetAttribute(bgemm_qkv_kernel,
                         cudaFuncAttributeMaxDynamicSharedMemorySize, GSMEM);
    cudaFuncSetAttribute(bgemm_o_kernel,
                         cudaFuncAttributeMaxDynamicSharedMemorySize, GSMEM);

    void *pq, *pk, *pv, *pao, *pxh, *pxl, *paoh, *paol, *pwth, *pwtl;
    cudaGetSymbolAddress(&pq,   g_q);
    cudaGetSymbolAddress(&pk,   g_k);
    cudaGetSymbolAddress(&pv,   g_v);
    cudaGetSymbolAddress(&pao,  g_ao);
    cudaGetSymbolAddress(&pxh,  g_xh);
    cudaGetSymbolAddress(&pxl,  g_xl);
    cudaGetSymbolAddress(&paoh, g_aoh);
    cudaGetSymbolAddress(&paol, g_aol);
    cudaGetSymbolAddress(&pwth, g_wth);
    cudaGetSymbolAddress(&pwtl, g_wtl);

    __nv_bfloat16* wth = (__nv_bfloat16*)pwth;
    __nv_bfloat16* wtl = (__nv_bfloat16*)pwtl;

    // 1. RoPE table
    rope_table_kernel<<<64, 1024>>>();

    // 2. operand conversion: x split + 4 weight transpose-splits
    split_kernel<<<(MTOT * DM) / 256, 256>>>(x, (__nv_bfloat16*)pxh,
                                             (__nv_bfloat16*)pxl, MTOT * DM);
    dim3 tg(DM / 32, DM / 32), tb(32, 8);
    transpose_split_kernel<<<tg, tb>>>(Wq, wth + 0 * DM * DM, wtl + 0 * DM * DM);
    transpose_split_kernel<<<tg, tb>>>(Wk, wth + 1 * DM * DM, wtl + 1 * DM * DM);
    transpose_split_kernel<<<tg, tb>>>(Wv, wth + 2 * DM * DM, wtl + 2 * DM * DM);
    transpose_split_kernel<<<tg, tb>>>(Wo, wth + 3 * DM * DM, wtl + 3 * DM * DM);

    // 3. fused QKV projections on tensor cores
    dim3 gqkv(DM / 128, MTOT / 128, 3);  // (8, 32, 3)
    bgemm_qkv_kernel<<<gqkv, 256, GSMEM>>>((__nv_bfloat16*)pxh,
                                           (__nv_bfloat16*)pxl,
                                           (float*)pq, (float*)pk, (float*)pv);

    // 4. RMSNorm + RoPE on q and k
    norm_rope_kernel<<<(2 * MTOT * NH) / 8, 256>>>(qw, kw);

    // 5. causal flash attention
    flash_kernel<<<dim3(TLEN / 64, BSZ * NH), 256, FLASH_SMEM>>>();

    // 6. split attention output, then output projection
    split_kernel<<<(MTOT * DM) / 256, 256>>>((const float*)pao,
                                             (__nv_bfloat16*)paoh,
                                             (__nv_bfloat16*)paol, MTOT * DM);
    dim3 go(DM / 128, MTOT / 128, 1);
    bgemm_o_kernel<<<go, 256, GSMEM>>>((__nv_bfloat16*)paoh,
                                       (__nv_bfloat16*)paol, out);
}

// round 16
// speedup vs baseline: 1.5144x; 1.0060x over previous
#include <cuda_runtime.h>
#include <cuda_bf16.h>
#include <math.h>
#include <stdint.h>

#define BSZ   2
#define TLEN  2048
#define DM    1024
#define NH    16
#define HD    64
#define MTOT  (BSZ * TLEN)   // 4096

// ---------------- scratch (device globals; no allocations) ----------------
__device__ float g_q [MTOT * DM];
__device__ float g_k [MTOT * DM];
__device__ float g_v [MTOT * DM];
__device__ float g_ao[MTOT * DM];
__device__ float g_cos[TLEN * 32];
__device__ float g_sin[TLEN * 32];

// bf16 hi/lo split operands for tensor-core GEMMs
__device__ __nv_bfloat16 g_xh [MTOT * DM];
__device__ __nv_bfloat16 g_xl [MTOT * DM];
__device__ __nv_bfloat16 g_aoh[MTOT * DM];
__device__ __nv_bfloat16 g_aol[MTOT * DM];
// transposed weights (Wt[n][k] = W[k][n]), hi/lo, for Wq,Wk,Wv,Wo
__device__ __nv_bfloat16 g_wth[4][DM * DM];
__device__ __nv_bfloat16 g_wtl[4][DM * DM];

// ================= helpers ==================================================
__device__ __forceinline__ uint32_t smem_u32(const void* p) {
    uint32_t a;
    asm("{ .reg .u64 t; cvta.to.shared.u64 t, %1; cvt.u32.u64 %0, t; }"
        : "=r"(a) : "l"(p));
    return a;
}
__device__ __forceinline__ void cp16(uint32_t s, const void* g) {
    asm volatile("cp.async.ca.shared.global [%0], [%1], 16;" :: "r"(s), "l"(g));
}
#define CP_COMMIT() asm volatile("cp.async.commit_group;" ::: "memory")
#define CP_WAIT(n)  asm volatile("cp.async.wait_group %0;" :: "n"(n) : "memory")

__device__ __forceinline__ void ldm_x4(uint32_t* r, uint32_t addr) {
    asm volatile("ldmatrix.sync.aligned.m8n8.x4.shared.b16 {%0,%1,%2,%3}, [%4];"
                 : "=r"(r[0]), "=r"(r[1]), "=r"(r[2]), "=r"(r[3]) : "r"(addr));
}
__device__ __forceinline__ void mma16816(float* d, const uint32_t* a,
                                         uint32_t b0, uint32_t b1) {
    asm volatile(
        "mma.sync.aligned.m16n8k16.row.col.f32.bf16.bf16.f32 "
        "{%0,%1,%2,%3}, {%4,%5,%6,%7}, {%8,%9}, {%0,%1,%2,%3};"
        : "+f"(d[0]), "+f"(d[1]), "+f"(d[2]), "+f"(d[3])
        : "r"(a[0]), "r"(a[1]), "r"(a[2]), "r"(a[3]), "r"(b0), "r"(b1));
}

// ---------------- RoPE table ----------------------------------------------
__global__ void rope_table_kernel() {
    int idx = blockIdx.x * blockDim.x + threadIdx.x;
    if (idx >= TLEN * 32) return;
    int t = idx >> 5;
    int i = idx & 31;
    double inv = pow(10000.0, -((double)(2 * i)) / 64.0);
    double f = (double)t * inv;
    g_cos[idx] = (float)cos(f);
    g_sin[idx] = (float)sin(f);
}

// ---------------- fp32 -> bf16 hi/lo split ---------------------------------
__global__ void split_kernel(const float* __restrict__ in,
                             __nv_bfloat16* __restrict__ h,
                             __nv_bfloat16* __restrict__ l, int n)
{
    int i = blockIdx.x * blockDim.x + threadIdx.x;
    if (i >= n) return;
    float v = in[i];
    __nv_bfloat16 hb = __float2bfloat16_rn(v);
    h[i] = hb;
    l[i] = __float2bfloat16_rn(v - __bfloat162float(hb));
}

// ---------------- W[k][n] -> Wt[n][k] transpose + hi/lo split --------------
__global__ void transpose_split_kernel(const float* __restrict__ W,
                                       __nv_bfloat16* __restrict__ th,
                                       __nv_bfloat16* __restrict__ tl)
{
    __shared__ float tile[32][33];
    int x = blockIdx.x * 32 + threadIdx.x;
    int y0 = blockIdx.y * 32 + threadIdx.y;
#pragma unroll
    for (int i = 0; i < 32; i += 8)
        tile[threadIdx.y + i][threadIdx.x] = W[(size_t)(y0 + i) * DM + x];
    __syncthreads();
    int nx = blockIdx.y * 32 + threadIdx.x;
    int ny0 = blockIdx.x * 32 + threadIdx.y;
#pragma unroll
    for (int i = 0; i < 32; i += 8) {
        float v = tile[threadIdx.x][threadIdx.y + i];
        __nv_bfloat16 hb = __float2bfloat16_rn(v);
        th[(size_t)(ny0 + i) * DM + nx] = hb;
        tl[(size_t)(ny0 + i) * DM + nx] =
            __float2bfloat16_rn(v - __bfloat162float(hb));
    }
}

// ---------------- split-bf16 tensor-core GEMM -------------------------------
// C[M,N] = A[M,K] @ Wt^T.  A given as (Ah + Al), Wt as (Bh + Bl), both
// row-major with K contiguous.  Products hh + hl + lh accumulated in fp32.
// 128x128 CTA tile, BK=32, 8 warps (2x4), warp tile 64x32, cp.async pipeline.
#define GLDA   40                      // padded row stride (bf16 elems)
#define GTILEB (128 * GLDA * 2)        // 10240 B per tensor tile
#define GSTAGE (4 * GTILEB)            // 40960 B per stage
#define GSMEM  (2 * GSTAGE)            // 81920 B total

__device__ __forceinline__ void gemm_prefetch(
    uint32_t sbase, int stage,
    const __nv_bfloat16* Ah, const __nv_bfloat16* Al,
    const __nv_bfloat16* Bh, const __nv_bfloat16* Bl,
    int tileM, int tileN, int k0, int tid)
{
    uint32_t st = sbase + stage * GSTAGE;
#pragma unroll
    for (int i = 0; i < 8; i++) {
        int c = tid + i * 256;         // 0..2047
        int tensor = c >> 9;           // 0..3
        int idx = c & 511;
        int row = idx >> 2;
        int col = (idx & 3) * 8;       // bf16 elem offset
        uint32_t soff = st + tensor * GTILEB + row * 80 + (idx & 3) * 16;
        const __nv_bfloat16* gp;
        if (tensor == 0)      gp = Ah + (size_t)(tileM + row) * DM + k0 + col;
        else if (tensor == 1) gp = Al + (size_t)(tileM + row) * DM + k0 + col;
        else if (tensor == 2) gp = Bh + (size_t)(tileN + row) * DM + k0 + col;
        else                  gp = Bl + (size_t)(tileN + row) * DM + k0 + col;
        cp16(soff, gp);
    }
}

__device__ __forceinline__ void gemm_body(
    const __nv_bfloat16* Ah, const __nv_bfloat16* Al,
    const __nv_bfloat16* Bh, const __nv_bfloat16* Bl,
    float* __restrict__ C, char* smraw)
{
    uint32_t sbase = smem_u32(smraw);
    int tid = threadIdx.x;
    int wid = tid >> 5, lane = tid & 31;
    int tileM = blockIdx.y * 128;
    int tileN = blockIdx.x * 128;
    int wm = (wid >> 2) * 64;
    int wn = (wid & 3) * 32;

    float acc[4][4][4];
#pragma unroll
    for (int i = 0; i < 4; i++)
#pragma unroll
        for (int j = 0; j < 4; j++)
#pragma unroll
            for (int r = 0; r < 4; r++) acc[i][j][r] = 0.f;

    gemm_prefetch(sbase, 0, Ah, Al, Bh, Bl, tileM, tileN, 0, tid);
    CP_COMMIT();

    int arow = lane & 15;
    int acol = (lane >> 4) * 8;
    int brow = ((lane >> 4) << 3) + (lane & 7);
    int bcol = ((lane >> 3) & 1) * 8;

    for (int c = 0; c < 32; c++) {
        if (c < 31) {
            gemm_prefetch(sbase, (c + 1) & 1, Ah, Al, Bh, Bl,
                          tileM, tileN, (c + 1) * 32, tid);
            CP_COMMIT();
            CP_WAIT(1);
        } else {
            CP_WAIT(0);
        }
        __syncthreads();

        uint32_t st = sbase + (c & 1) * GSTAGE;
#pragma unroll
        for (int kk = 0; kk < 32; kk += 16) {
            uint32_t ah[4][4], al[4][4];
#pragma unroll
            for (int mt = 0; mt < 4; mt++) {
                uint32_t ad = st + ((wm + mt * 16 + arow) * GLDA + kk + acol) * 2;
                ldm_x4(ah[mt], ad);
                ldm_x4(al[mt], ad + GTILEB);
            }
            uint32_t bh[2][4], bl[2][4];
#pragma unroll
            for (int p = 0; p < 2; p++) {
                uint32_t bd = st + 2 * GTILEB +
                              ((wn + p * 16 + brow) * GLDA + kk + bcol) * 2;
                ldm_x4(bh[p], bd);
                ldm_x4(bl[p], bd + GTILEB);
            }
#pragma unroll
            for (int mt = 0; mt < 4; mt++)
#pragma unroll
                for (int nt = 0; nt < 4; nt++) {
                    int p = nt >> 1, o = (nt & 1) * 2;
                    mma16816(acc[mt][nt], ah[mt], bh[p][o], bh[p][o + 1]);
                    mma16816(acc[mt][nt], ah[mt], bl[p][o], bl[p][o + 1]);
                    mma16816(acc[mt][nt], al[mt], bh[p][o], bh[p][o + 1]);
                }
        }
        __syncthreads();
    }

    // epilogue
#pragma unroll
    for (int mt = 0; mt < 4; mt++) {
        int row = tileM + wm + mt * 16 + (lane >> 2);
#pragma unroll
        for (int nt = 0; nt < 4; nt++) {
            int col = tileN + wn + nt * 8 + (lane & 3) * 2;
            float2 v0 = make_float2(acc[mt][nt][0], acc[mt][nt][1]);
            float2 v1 = make_float2(acc[mt][nt][2], acc[mt][nt][3]);
            *(float2*)(C + (size_t)row * DM + col)       = v0;
            *(float2*)(C + (size_t)(row + 8) * DM + col) = v1;
        }
    }
}

// fused QKV: blockIdx.z selects weight slot and destination
__global__ __launch_bounds__(256) void bgemm_qkv_kernel(
    const __nv_bfloat16* __restrict__ Ah, const __nv_bfloat16* __restrict__ Al,
    float* __restrict__ C0, float* __restrict__ C1, float* __restrict__ C2)
{
    extern __shared__ char smraw[];
    int z = blockIdx.z;
    float* C = (z == 0) ? C0 : (z == 1) ? C1 : C2;
    gemm_body(Ah, Al, g_wth[z], g_wtl[z], C, smraw);
}

__global__ __launch_bounds__(256) void bgemm_o_kernel(
    const __nv_bfloat16* __restrict__ Ah, const __nv_bfloat16* __restrict__ Al,
    float* __restrict__ C)
{
    extern __shared__ char smraw[];
    gemm_body(Ah, Al, g_wth[3], g_wtl[3], C, smraw);
}

// ---------------- fused per-head RMSNorm + RoPE ----------------------------
__global__ void norm_rope_kernel(const float* __restrict__ qw,
                                 const float* __restrict__ kw)
{
    int gw = (blockIdx.x * blockDim.x + threadIdx.x) >> 5;
    int lane = threadIdx.x & 31;
    int which = gw >> 16;
    int row = gw & 65535;
    float* base = which ? g_k : g_q;
    const float* w = which ? kw : qw;

    int bt = row / NH;
    int h  = row % NH;
    int t  = bt % TLEN;

    float* p = base + (size_t)bt * DM + h * HD;
    float x1 = p[lane];
    float x2 = p[lane + 32];

    float ss = x1 * x1 + x2 * x2;
#pragma unroll
    for (int o = 16; o; o >>= 1) ss += __shfl_xor_sync(0xffffffffu, ss, o);
    float r = rsqrtf(ss * (1.0f / 64.0f) + 1e-6f);

    float c = g_cos[t * 32 + lane];
    float s = g_sin[t * 32 + lane];
    float x1n = x1 * r * w[lane];
    float x2n = x2 * r * w[lane + 32];
    p[lane]      = x1n * c - x2n * s;
    p[lane + 32] = x2n * c + x1n * s;
}

// ---------------- flash attention (causal, fp32, 64x64 tiles) --------------
#define FP    68
#define SM_Q  0
#define SM_KT (64 * FP)
#define SM_V  (2 * 64 * FP)
#define SM_P  (3 * 64 * FP)
#define SM_M  (4 * 64 * FP)
#define SM_L  (SM_M + 64)
#define SM_A  (SM_L + 64)
#define FLASH_SMEM ((4 * 64 * FP + 3 * 64) * 4)

__global__ __launch_bounds__(256) void flash_kernel()
{
    extern __shared__ float sm[];
    float* Qs  = sm + SM_Q;
    float* KsT = sm + SM_KT;
    float* Vs  = sm + SM_V;
    float* Ps  = sm + SM_P;
    float* mrow = sm + SM_M;
    float* lrow = sm + SM_L;
    float* arow = sm + SM_A;

    int qt = gridDim.x - 1 - blockIdx.x;
    int bh = blockIdx.y;
    int b = bh / NH, h = bh % NH;
    int tid = threadIdx.x;
    int tx = tid & 15, ty = tid >> 4;

    const float* qbase = g_q + (size_t)(b * TLEN) * DM + h * HD;
    const float* kbase = g_k + (size_t)(b * TLEN) * DM + h * HD;
    const float* vbase = g_v + (size_t)(b * TLEN) * DM + h * HD;

    for (int it = tid; it < 64 * 16; it += 256) {
        int r = it >> 4;
        int c4 = (it & 15) << 2;
        float4 v = *(const float4*)(qbase + (size_t)(qt * 64 + r) * DM + c4);
        *(float4*)&Qs[r * FP + c4] = v;
    }
    if (tid < 64) { mrow[tid] = -INFINITY; lrow[tid] = 0.f; }

    float o[4][4];
#pragma unroll
    for (int i = 0; i < 4; i++)
#pragma unroll
        for (int j = 0; j < 4; j++) o[i][j] = 0.f;

    const float scale = 0.125f;

    for (int kt = 0; kt <= qt; kt++) {
        __syncthreads();
        for (int it = tid; it < 64 * 16; it += 256) {
            int r = it >> 4;
            int c4 = (it & 15) << 2;
            const float* kp = kbase + (size_t)(kt * 64 + r) * DM + c4;
            float4 kv = *(const float4*)kp;
            KsT[(c4 + 0) * FP + r] = kv.x;
            KsT[(c4 + 1) * FP + r] = kv.y;
            KsT[(c4 + 2) * FP + r] = kv.z;
            KsT[(c4 + 3) * FP + r] = kv.w;
            const float* vp = vbase + (size_t)(kt * 64 + r) * DM + c4;
            *(float4*)&Vs[r * FP + c4] = *(const float4*)vp;
        }
        __syncthreads();

        float s[4][4];
#pragma unroll
        for (int i = 0; i < 4; i++)
#pragma unroll
            for (int j = 0; j < 4; j++) s[i][j] = 0.f;

#pragma unroll 8
        for (int d = 0; d < 64; d++) {
            float4 k4 = *(const float4*)&KsT[d * FP + tx * 4];
#pragma unroll
            for (int ii = 0; ii < 4; ii++) {
                float qv = Qs[(ty * 4 + ii) * FP + d];
                s[ii][0] += qv * k4.x;
                s[ii][1] += qv * k4.y;
                s[ii][2] += qv * k4.z;
                s[ii][3] += qv * k4.w;
            }
        }

        bool diag = (kt == qt);
        float rmax[4];
#pragma unroll
        for (int ii = 0; ii < 4; ii++) {
            rmax[ii] = -INFINITY;
#pragma unroll
            for (int jj = 0; jj < 4; jj++) {
                float v = s[ii][jj] * scale;
                if (diag && (tx * 4 + jj) > (ty * 4 + ii)) v = -INFINITY;
                s[ii][jj] = v;
                rmax[ii] = fmaxf(rmax[ii], v);
            }
#pragma unroll
            for (int off = 8; off; off >>= 1)
                rmax[ii] = fmaxf(rmax[ii], __shfl_xor_sync(0xffffffffu, rmax[ii], off));
        }
        if (tx == 0) {
#pragma unroll
            for (int ii = 0; ii < 4; ii++) {
                int i = ty * 4 + ii;
                float mo = mrow[i];
                float mn = fmaxf(mo, rmax[ii]);
                mrow[i] = mn;
                arow[i] = expf(mo - mn);
            }
        }
        __syncthreads();

        float rsum[4];
#pragma unroll
        for (int ii = 0; ii < 4; ii++) {
            int i = ty * 4 + ii;
            float mi = mrow[i];
            float a  = arow[i];
            rsum[ii] = 0.f;
#pragma unroll
            for (int jj = 0; jj < 4; jj++) {
                float p = expf(s[ii][jj] - mi);
                Ps[i * FP + tx * 4 + jj] = p;
                rsum[ii] += p;
                o[ii][jj] *= a;
            }
#pragma unroll
            for (int off = 8; off; off >>= 1)
                rsum[ii] += __shfl_xor_sync(0xffffffffu, rsum[ii], off);
        }
        if (tx == 0) {
#pragma unroll
            for (int ii = 0; ii < 4; ii++) {
                int i = ty * 4 + ii;
                lrow[i] = lrow[i] * arow[i] + rsum[ii];
            }
        }
        __syncthreads();

#pragma unroll 8
        for (int kk = 0; kk < 64; kk++) {
            float4 v4 = *(const float4*)&Vs[kk * FP + tx * 4];
#pragma unroll
            for (int ii = 0; ii < 4; ii++) {
                float pv = Ps[(ty * 4 + ii) * FP + kk];
                o[ii][0] += pv * v4.x;
                o[ii][1] += pv * v4.y;
                o[ii][2] += pv * v4.z;
                o[ii][3] += pv * v4.w;
            }
        }
    }

#pragma unroll
    for (int ii = 0; ii < 4; ii++) {
        int i = ty * 4 + ii;
        float inv = 1.0f / lrow[i];
        int row = qt * 64 + i;
        float4 ov = make_float4(o[ii][0] * inv, o[ii][1] * inv,
                                o[ii][2] * inv, o[ii][3] * inv);
        *(float4*)(g_ao + (size_t)(b * TLEN + row) * DM + h * HD + tx * 4) = ov;
    }
}

// ---------------- launch ----------------------------------------------------
extern "C" void kernel_launch(void* const* d_in, const int* in_sizes, int n_in,
                              void* d_out, int out_size)
{
    const float* x  = (const float*)d_in[0];
    const float* Wq = (const float*)d_in[1];
    const float* Wk = (const float*)d_in[2];
    const float* Wv = (const float*)d_in[3];
    const float* Wo = (const float*)d_in[4];
    const float* qw = (const float*)d_in[5];
    const float* kw = (const float*)d_in[6];
    float* out = (float*)d_out;

    cudaFuncSetAttribute(flash_kernel,
                         cudaFuncAttributeMaxDynamicSharedMemorySize, FLASH_SMEM);
    cudaFuncSetAttribute(bgemm_qkv_kernel,
                         cudaFuncAttributeMaxDynamicSharedMemorySize, GSMEM);
    cudaFuncSetAttribute(bgemm_o_kernel,
                         cudaFuncAttributeMaxDynamicSharedMemorySize, GSMEM);

    void *pq, *pk, *pv, *pao, *pxh, *pxl, *paoh, *paol, *pwth, *pwtl;
    cudaGetSymbolAddress(&pq,   g_q);
    cudaGetSymbolAddress(&pk,   g_k);
    cudaGetSymbolAddress(&pv,   g_v);
    cudaGetSymbolAddress(&pao,  g_ao);
    cudaGetSymbolAddress(&pxh,  g_xh);
    cudaGetSymbolAddress(&pxl,  g_xl);
    cudaGetSymbolAddress(&paoh, g_aoh);
    cudaGetSymbolAddress(&paol, g_aol);
    cudaGetSymbolAddress(&pwth, g_wth);
    cudaGetSymbolAddress(&pwtl, g_wtl);

    __nv_bfloat16* wth = (__nv_bfloat16*)pwth;
    __nv_bfloat16* wtl = (__nv_bfloat16*)pwtl;

    // 1. RoPE table
    rope_table_kernel<<<64, 1024>>>();

    // 2. operand conversion: x split + 4 weight transpose-splits
    split_kernel<<<(MTOT * DM) / 256, 256>>>(x, (__nv_bfloat16*)pxh,
                                             (__nv_bfloat16*)pxl, MTOT * DM);
    dim3 tg(DM / 32, DM / 32), tb(32, 8);
    transpose_split_kernel<<<tg, tb>>>(Wq, wth + 0 * DM * DM, wtl + 0 * DM * DM);
    transpose_split_kernel<<<tg, tb>>>(Wk, wth + 1 * DM * DM, wtl + 1 * DM * DM);
    transpose_split_kernel<<<tg, tb>>>(Wv, wth + 2 * DM * DM, wtl + 2 * DM * DM);
    transpose_split_kernel<<<tg, tb>>>(Wo, wth + 3 * DM * DM, wtl + 3 * DM * DM);

    // 3. fused QKV projections on tensor cores
    dim3 gqkv(DM / 128, MTOT / 128, 3);  // (8, 32, 3)
    bgemm_qkv_kernel<<<gqkv, 256, GSMEM>>>((__nv_bfloat16*)pxh,
                                           (__nv_bfloat16*)pxl,
                                           (float*)pq, (float*)pk, (float*)pv);

    // 4. RMSNorm + RoPE on q and k
    norm_rope_kernel<<<(2 * MTOT * NH) / 8, 256>>>(qw, kw);

    // 5. causal flash attention
    flash_kernel<<<dim3(TLEN / 64, BSZ * NH), 256, FLASH_SMEM>>>();

    // 6. split attention output, then output projection
    split_kernel<<<(MTOT * DM) / 256, 256>>>((const float*)pao,
                                             (__nv_bfloat16*)paoh,
                                             (__nv_bfloat16*)paol, MTOT * DM);
    dim3 go(DM / 128, MTOT / 128, 1);
    bgemm_o_kernel<<<go, 256, GSMEM>>>((__nv_bfloat16*)paoh,
                                       (__nv_bfloat16*)paol, out);
}